// round 3
// baseline (speedup 1.0000x reference)
#include <cuda_runtime.h>
#include <cuda_fp16.h>
#include <cstdint>

#define NNODES 8192
#define NEDGES 262144
#define DIN    512
#define DH     256
#define ALPHA  0.1520f
#define BETA   0.7900f

// ---------------- scratch (device globals; no allocation allowed) ----------
__device__ float  g_deg [NNODES];
__device__ float  g_dinv[NNODES];
__device__ float  g_Y1  [NNODES * DH];    // X @ W1 (fp32)
__device__ __half g_Y1h [NNODES * DH];    // X @ W1 (fp16 copy for prop gather)
__device__ float  g_P1  [NNODES * DH];    // edge-aggregated Y1 (atomic target)
__device__ float  g_Y2  [NNODES * 2];     // relu(prop1+b1) @ W2
__device__ float  g_eacc[NNODES * 2];     // edge-aggregated Y2 (atomic target)
__device__ float  g_ex  [NNODES];
__device__ float  g_ey  [NNODES];

// ---------------- zero accumulators (must run every replay) ----------------
__global__ void zero_kernel() {
    int idx = blockIdx.x * blockDim.x + threadIdx.x;
    float4 z = make_float4(0.f, 0.f, 0.f, 0.f);
    if (idx < NNODES * DH / 4) ((float4*)g_P1)[idx] = z;
    if (idx < NNODES * 2 / 4)  ((float4*)g_eacc)[idx] = z;
    if (idx < NNODES / 4)      ((float4*)g_deg)[idx] = z;
}

// ---------------- degree (in-degree of dst) --------------------------------
__global__ void deg_kernel(const int* __restrict__ dst) {
    int e = blockIdx.x * blockDim.x + threadIdx.x;
    if (e < NEDGES) atomicAdd(&g_deg[dst[e]], 1.0f);
}

__global__ void dinv_kernel() {
    int i = blockIdx.x * blockDim.x + threadIdx.x;
    if (i < NNODES) g_dinv[i] = rsqrtf(g_deg[i] + 1.0f);
}

// ---------------- GEMM1: Y1[8192,256] = X[8192,512] @ W1[512,256] ----------
// BM=64 BN=64 BK=32, 256 threads, 4x4 per thread, packed fma.rn.f32x2.
#define FFMA2(d, a, b) asm("fma.rn.f32x2 %0, %1, %2, %0;" : "+l"(d) : "l"(a), "l"(b))

__global__ __launch_bounds__(256) void gemm1_kernel(const float* __restrict__ X,
                                                    const float* __restrict__ W1) {
    __shared__ float As[32][68];    // [k][m], padded
    __shared__ float Bs[32][132];   // [k][n duplicated: b0,b0,b1,b1,...], padded
    const int bm = blockIdx.y * 64;
    const int bn = blockIdx.x * 64;
    const int tid = threadIdx.x;
    const int tx = tid & 15;        // n-group (4 cols)
    const int ty = tid >> 4;        // m-group (4 rows)

    unsigned long long acc2[2][4];  // [m-pair][n], each holds (m_lo, m_hi)
#pragma unroll
    for (int a = 0; a < 2; a++)
#pragma unroll
        for (int b = 0; b < 4; b++) acc2[a][b] = 0ull;

    for (int k0 = 0; k0 < DIN; k0 += 32) {
        // A tile (64 x 32) -> As[k][m]
#pragma unroll
        for (int it = 0; it < 2; ++it) {
            int r = (tid >> 3) + it * 32;        // 0..63
            int c = (tid & 7) << 2;              // 0..28
            float4 v = *(const float4*)&X[(size_t)(bm + r) * DIN + k0 + c];
            As[c + 0][r] = v.x; As[c + 1][r] = v.y;
            As[c + 2][r] = v.z; As[c + 3][r] = v.w;
        }
        // B tile (32 x 64) -> Bs[k][dup-n] with each value duplicated
#pragma unroll
        for (int it = 0; it < 2; ++it) {
            int r = (tid >> 4) + it * 16;        // 0..31
            int c = (tid & 15) << 2;             // 0..60
            float4 w = *(const float4*)&W1[(size_t)(k0 + r) * DH + bn + c];
            float4 d0 = make_float4(w.x, w.x, w.y, w.y);
            float4 d1 = make_float4(w.z, w.z, w.w, w.w);
            *(float4*)&Bs[r][2 * c + 0] = d0;
            *(float4*)&Bs[r][2 * c + 4] = d1;
        }
        __syncthreads();
#pragma unroll
        for (int k = 0; k < 32; ++k) {
            ulonglong2 aa  = *(const ulonglong2*)&As[k][ty << 2];       // (m0,m1),(m2,m3)
            ulonglong2 b01 = *(const ulonglong2*)&Bs[k][tx << 3];       // splat n0, splat n1
            ulonglong2 b23 = *(const ulonglong2*)&Bs[k][(tx << 3) + 4]; // splat n2, splat n3
            FFMA2(acc2[0][0], aa.x, b01.x);
            FFMA2(acc2[0][1], aa.x, b01.y);
            FFMA2(acc2[0][2], aa.x, b23.x);
            FFMA2(acc2[0][3], aa.x, b23.y);
            FFMA2(acc2[1][0], aa.y, b01.x);
            FFMA2(acc2[1][1], aa.y, b01.y);
            FFMA2(acc2[1][2], aa.y, b23.x);
            FFMA2(acc2[1][3], aa.y, b23.y);
        }
        __syncthreads();
    }
#pragma unroll
    for (int mp = 0; mp < 2; ++mp) {
#pragma unroll
        for (int h = 0; h < 2; ++h) {
            float4 v;
            float2 f0 = *(float2*)&acc2[mp][0];
            float2 f1 = *(float2*)&acc2[mp][1];
            float2 f2 = *(float2*)&acc2[mp][2];
            float2 f3 = *(float2*)&acc2[mp][3];
            v.x = h ? f0.y : f0.x;
            v.y = h ? f1.y : f1.x;
            v.z = h ? f2.y : f2.x;
            v.w = h ? f3.y : f3.x;
            int row = bm + (ty << 2) + mp * 2 + h;
            *(float4*)&g_Y1[(size_t)row * DH + bn + (tx << 2)] = v;
            __half2 h01 = __floats2half2_rn(v.x, v.y);
            __half2 h23 = __floats2half2_rn(v.z, v.w);
            uint2 pk;
            pk.x = *(unsigned*)&h01;
            pk.y = *(unsigned*)&h23;
            *(uint2*)&g_Y1h[(size_t)row * DH + bn + (tx << 2)] = pk;
        }
    }
}

// ---------------- prop1: P1[dst] += Y1h[src] * (dinv[src]*dinv[dst]) -------
// one warp per edge; lane handles 8 halfs (16B gather) -> 2 x red.v4.f32
__global__ __launch_bounds__(256) void prop1_kernel(const int* __restrict__ src,
                                                    const int* __restrict__ dst) {
    int w = (blockIdx.x * blockDim.x + threadIdx.x) >> 5;
    int lane = threadIdx.x & 31;
    if (w >= NEDGES) return;
    int s = __ldg(&src[w]);
    int d = __ldg(&dst[w]);
    float nrm = g_dinv[s] * g_dinv[d];
    const uint4* yrow = (const uint4*)(g_Y1h + (size_t)s * DH);   // 32 x 16B
    float* prow = g_P1 + (size_t)d * DH + (lane << 3);
    uint4 v = __ldg(&yrow[lane]);
    float2 f0 = __half22float2(*(__half2*)&v.x);
    float2 f1 = __half22float2(*(__half2*)&v.y);
    float2 f2 = __half22float2(*(__half2*)&v.z);
    float2 f3 = __half22float2(*(__half2*)&v.w);
    asm volatile("red.global.add.v4.f32 [%0], {%1,%2,%3,%4};"
                 :: "l"(prow), "f"(f0.x * nrm), "f"(f0.y * nrm),
                    "f"(f1.x * nrm), "f"(f1.y * nrm) : "memory");
    asm volatile("red.global.add.v4.f32 [%0], {%1,%2,%3,%4};"
                 :: "l"(prow + 4), "f"(f2.x * nrm), "f"(f2.y * nrm),
                    "f"(f3.x * nrm), "f"(f3.y * nrm) : "memory");
}

// ---------------- node fuse: h = relu(P1 + Y1*dinv^2 + b1); Y2 = h @ W2 ----
__global__ __launch_bounds__(256) void node2_kernel(const float* __restrict__ b1,
                                                    const float* __restrict__ W2) {
    int node = (blockIdx.x * blockDim.x + threadIdx.x) >> 5;
    int lane = threadIdx.x & 31;
    if (node >= NNODES) return;
    float di = g_dinv[node];
    float di2 = di * di;
    const float* prow = g_P1 + (size_t)node * DH;
    const float* yrow = g_Y1 + (size_t)node * DH;
    const float2* w2 = (const float2*)W2;
    float s0 = 0.f, s1 = 0.f;
#pragma unroll
    for (int j = 0; j < DH / 32; ++j) {
        int d = lane + j * 32;
        float h = prow[d] + yrow[d] * di2 + b1[d];
        h = fmaxf(h, 0.f);
        float2 w = __ldg(&w2[d]);
        s0 = fmaf(h, w.x, s0);
        s1 = fmaf(h, w.y, s1);
    }
#pragma unroll
    for (int off = 16; off > 0; off >>= 1) {
        s0 += __shfl_down_sync(0xffffffffu, s0, off);
        s1 += __shfl_down_sync(0xffffffffu, s1, off);
    }
    if (lane == 0) {
        g_Y2[node * 2 + 0] = s0;
        g_Y2[node * 2 + 1] = s1;
    }
}

// ---------------- prop2: eacc[dst] += Y2[src] * norm (2-dim) ---------------
__global__ void prop2_kernel(const int* __restrict__ src, const int* __restrict__ dst) {
    int e = blockIdx.x * blockDim.x + threadIdx.x;
    if (e >= NEDGES) return;
    int s = src[e], d = dst[e];
    float nrm = g_dinv[s] * g_dinv[d];
    float2 y = ((const float2*)g_Y2)[s];
    float* p = g_eacc + (size_t)d * 2;
    asm volatile("red.global.add.v2.f32 [%0], {%1,%2};"
                 :: "l"(p), "f"(y.x * nrm), "f"(y.y * nrm) : "memory");
}

// ---------------- finalize emb -------------------------------------------
__global__ void fin_kernel(const float* __restrict__ b2, float* __restrict__ out) {
    int i = blockIdx.x * blockDim.x + threadIdx.x;
    if (i >= NNODES) return;
    float di = g_dinv[i];
    float di2 = di * di;
    float2 y = ((const float2*)g_Y2)[i];
    float ex = g_eacc[2 * i + 0] + y.x * di2 + b2[0];
    float ey = g_eacc[2 * i + 1] + y.y * di2 + b2[1];
    g_ex[i] = ex;
    g_ey[i] = ey;
    out[2 * i + 0] = ex;
    out[2 * i + 1] = ey;
}

// ---------------- q[i,j] = 1/(1 + alpha * (d2)^beta) -----------------------
__device__ __forceinline__ float qval(float dx, float dy) {
    float d2 = fmaf(dx, dx, dy * dy);
    float pw = __powf(d2, BETA);
    float q  = __fdividef(1.0f, fmaf(ALPHA, pw, 1.0f));
    return d2 > 0.0f ? q : 1.0f;
}

__global__ __launch_bounds__(256) void q_kernel(float* __restrict__ qout) {
    int i = blockIdx.y * 8 + (threadIdx.x >> 5);
    int j = (blockIdx.x << 7) + ((threadIdx.x & 31) << 2);
    float xi = g_ex[i];
    float yi = g_ey[i];
    float4 xj = *(const float4*)&g_ex[j];
    float4 yj = *(const float4*)&g_ey[j];
    float4 r;
    r.x = qval(xi - xj.x, yi - yj.x);
    r.y = qval(xi - xj.y, yi - yj.y);
    r.z = qval(xi - xj.z, yi - yj.z);
    r.w = qval(xi - xj.w, yi - yj.w);
    *(float4*)&qout[(size_t)i * NNODES + j] = r;
}

// ---------------------------------------------------------------------------
extern "C" void kernel_launch(void* const* d_in, const int* in_sizes, int n_in,
                              void* d_out, int out_size) {
    const float* X  = (const float*)d_in[0];   // [8192,512]
    const int*   ei = (const int*)  d_in[1];   // [2,262144]
    const float* W1 = (const float*)d_in[2];   // [512,256]
    const float* b1 = (const float*)d_in[3];   // [256]
    const float* W2 = (const float*)d_in[4];   // [256,2]
    const float* b2 = (const float*)d_in[5];   // [2]
    float* out = (float*)d_out;                // emb (16384) then q (8192*8192)
    (void)in_sizes; (void)n_in; (void)out_size;

    const int* src = ei;
    const int* dst = ei + NEDGES;

    zero_kernel<<<(NNODES * DH / 4 + 255) / 256, 256>>>();
    deg_kernel<<<NEDGES / 256, 256>>>(dst);
    dinv_kernel<<<NNODES / 256, 256>>>();
    gemm1_kernel<<<dim3(DH / 64, NNODES / 64), 256>>>(X, W1);
    prop1_kernel<<<NEDGES * 32 / 256, 256>>>(src, dst);
    node2_kernel<<<NNODES * 32 / 256, 256>>>(b1, W2);
    prop2_kernel<<<NEDGES / 256, 256>>>(src, dst);
    fin_kernel<<<NNODES / 256, 256>>>(b2, out);
    q_kernel<<<dim3(NNODES / 128, NNODES / 8), 256>>>(out + NNODES * 2);
}

// round 5
// speedup vs baseline: 2.0551x; 2.0551x over previous
#include <cuda_runtime.h>
#include <cuda_bf16.h>
#include <cstdint>

#define NNODES 8192
#define NEDGES 262144
#define DIN    512
#define DH     256
#define ALPHA  0.1520f
#define BETA   0.7900f

// ---------------- scratch (device globals; no allocation allowed) ----------
__device__ float g_deg [NNODES];
__device__ float g_dinv[NNODES];
__device__ float g_Y1  [NNODES * DH];   // X @ W1
__device__ float g_P1  [NNODES * DH];   // edge-aggregated Y1 (atomic target)
__device__ float g_Y2  [NNODES * 2];
__device__ float g_eacc[NNODES * 2];
__device__ float g_ex  [NNODES];
__device__ float g_ey  [NNODES];

// ---------------- zero accumulators (must run every replay) ----------------
__global__ void zero_kernel() {
    int idx = blockIdx.x * blockDim.x + threadIdx.x;
    float4 z = make_float4(0.f, 0.f, 0.f, 0.f);
    if (idx < NNODES * DH / 4) ((float4*)g_P1)[idx] = z;
    if (idx < NNODES * 2 / 4)  ((float4*)g_eacc)[idx] = z;
    if (idx < NNODES / 4)      ((float4*)g_deg)[idx] = z;
}

__global__ void deg_kernel(const int* __restrict__ dst) {
    int e = blockIdx.x * blockDim.x + threadIdx.x;
    if (e < NEDGES) atomicAdd(&g_deg[dst[e]], 1.0f);
}

__global__ void dinv_kernel() {
    int i = blockIdx.x * blockDim.x + threadIdx.x;
    if (i < NNODES) g_dinv[i] = rsqrtf(g_deg[i] + 1.0f);
}

// ================= GEMM1 via mma.sync bf16 (3-term split) ==================
// Y1[8192,256] = X[8192,512] @ W1[512,256]
// CTA tile 128(m) x 64(n); K in chunks of 64; 8 warps -> each 32x32.
// smem: A_hi/A_lo 128x64 bf16 (16KB each), B_hi/B_lo 64x64 bf16 (8KB each).

#define SMEM_A_HI 0
#define SMEM_A_LO 16384
#define SMEM_B_HI 32768
#define SMEM_B_LO 40960
#define GEMM_SMEM 49152

__device__ __forceinline__ uint32_t smem_u32(const void* p) {
    uint32_t a;
    asm("{ .reg .u64 t; cvta.to.shared.u64 t, %1; cvt.u32.u64 %0, t; }" : "=r"(a) : "l"(p));
    return a;
}

__device__ __forceinline__ void ldmatrix_x4(uint32_t* r, uint32_t addr) {
    asm volatile("ldmatrix.sync.aligned.m8n8.x4.shared.b16 {%0,%1,%2,%3}, [%4];"
                 : "=r"(r[0]), "=r"(r[1]), "=r"(r[2]), "=r"(r[3]) : "r"(addr));
}
__device__ __forceinline__ void ldmatrix_x2t(uint32_t* r, uint32_t addr) {
    asm volatile("ldmatrix.sync.aligned.m8n8.x2.trans.shared.b16 {%0,%1}, [%2];"
                 : "=r"(r[0]), "=r"(r[1]) : "r"(addr));
}
__device__ __forceinline__ void mma_bf16(float* d, const uint32_t* a, const uint32_t* b) {
    asm volatile(
        "mma.sync.aligned.m16n8k16.row.col.f32.bf16.bf16.f32 "
        "{%0,%1,%2,%3}, {%4,%5,%6,%7}, {%8,%9}, {%0,%1,%2,%3};"
        : "+f"(d[0]), "+f"(d[1]), "+f"(d[2]), "+f"(d[3])
        : "r"(a[0]), "r"(a[1]), "r"(a[2]), "r"(a[3]), "r"(b[0]), "r"(b[1]));
}

__global__ __launch_bounds__(256) void gemm1_mma_kernel(const float* __restrict__ X,
                                                        const float* __restrict__ W1) {
    extern __shared__ __align__(1024) char sm[];
    const uint32_t sbase = smem_u32(sm);
    const int tid = threadIdx.x;
    const int wid = tid >> 5, lane = tid & 31;
    const int bm = blockIdx.y * 128;
    const int bn = blockIdx.x * 64;
    const int wm0 = (wid & 3) * 32;      // warp m offset within tile
    const int wn0 = (wid >> 2) * 32;     // warp n offset within tile

    float d[2][4][4];
#pragma unroll
    for (int mt = 0; mt < 2; ++mt)
#pragma unroll
        for (int nt = 0; nt < 4; ++nt)
#pragma unroll
            for (int u = 0; u < 4; ++u) d[mt][nt][u] = 0.f;

    for (int k0 = 0; k0 < DIN; k0 += 64) {
        // ---- load+convert A chunk: 128 rows x 64 k ----
#pragma unroll
        for (int p = 0; p < 8; ++p) {
            int r  = (tid >> 4) + p * 16;
            int c4 = (tid & 15) << 2;
            float4 v = __ldg((const float4*)&X[(size_t)(bm + r) * DIN + k0 + c4]);
            __nv_bfloat16 h0 = __float2bfloat16_rn(v.x);
            __nv_bfloat16 h1 = __float2bfloat16_rn(v.y);
            __nv_bfloat16 h2 = __float2bfloat16_rn(v.z);
            __nv_bfloat16 h3 = __float2bfloat16_rn(v.w);
            __nv_bfloat16 l0 = __float2bfloat16_rn(v.x - __bfloat162float(h0));
            __nv_bfloat16 l1 = __float2bfloat16_rn(v.y - __bfloat162float(h1));
            __nv_bfloat16 l2 = __float2bfloat16_rn(v.z - __bfloat162float(h2));
            __nv_bfloat16 l3 = __float2bfloat16_rn(v.w - __bfloat162float(h3));
            uint32_t off = (uint32_t)(r * 128 + c4 * 2);
            off ^= (uint32_t)(r & 7) << 4;
            uint2 ph, pl;
            ph.x = ((uint32_t)__bfloat16_as_ushort(h1) << 16) | __bfloat16_as_ushort(h0);
            ph.y = ((uint32_t)__bfloat16_as_ushort(h3) << 16) | __bfloat16_as_ushort(h2);
            pl.x = ((uint32_t)__bfloat16_as_ushort(l1) << 16) | __bfloat16_as_ushort(l0);
            pl.y = ((uint32_t)__bfloat16_as_ushort(l3) << 16) | __bfloat16_as_ushort(l2);
            *(uint2*)(sm + SMEM_A_HI + off) = ph;
            *(uint2*)(sm + SMEM_A_LO + off) = pl;
        }
        // ---- load+convert B chunk: 64 k-rows x 64 n ----
        {
            int r  = tid >> 2;                 // k row 0..63
            int cb = (tid & 3) << 4;           // n col base
#pragma unroll
            for (int j = 0; j < 4; ++j) {
                int c = cb + j * 4;
                float4 v = __ldg((const float4*)&W1[(size_t)(k0 + r) * DH + bn + c]);
                __nv_bfloat16 h0 = __float2bfloat16_rn(v.x);
                __nv_bfloat16 h1 = __float2bfloat16_rn(v.y);
                __nv_bfloat16 h2 = __float2bfloat16_rn(v.z);
                __nv_bfloat16 h3 = __float2bfloat16_rn(v.w);
                __nv_bfloat16 l0 = __float2bfloat16_rn(v.x - __bfloat162float(h0));
                __nv_bfloat16 l1 = __float2bfloat16_rn(v.y - __bfloat162float(h1));
                __nv_bfloat16 l2 = __float2bfloat16_rn(v.z - __bfloat162float(h2));
                __nv_bfloat16 l3 = __float2bfloat16_rn(v.w - __bfloat162float(h3));
                uint32_t off = (uint32_t)(r * 128 + c * 2);
                off ^= (uint32_t)(r & 7) << 4;
                uint2 ph, pl;
                ph.x = ((uint32_t)__bfloat16_as_ushort(h1) << 16) | __bfloat16_as_ushort(h0);
                ph.y = ((uint32_t)__bfloat16_as_ushort(h3) << 16) | __bfloat16_as_ushort(h2);
                pl.x = ((uint32_t)__bfloat16_as_ushort(l1) << 16) | __bfloat16_as_ushort(l0);
                pl.y = ((uint32_t)__bfloat16_as_ushort(l3) << 16) | __bfloat16_as_ushort(l2);
                *(uint2*)(sm + SMEM_B_HI + off) = ph;
                *(uint2*)(sm + SMEM_B_LO + off) = pl;
            }
        }
        __syncthreads();

#pragma unroll
        for (int ks = 0; ks < 4; ++ks) {
            const int kk = ks * 16;
            uint32_t ah[2][4], al[2][4], bh[4][2], bl[4][2];
#pragma unroll
            for (int mt = 0; mt < 2; ++mt) {
                int row = wm0 + mt * 16 + (lane & 15);
                uint32_t off = (uint32_t)(row * 128 + kk * 2 + ((lane >> 4) << 4));
                off ^= (uint32_t)(row & 7) << 4;
                ldmatrix_x4(ah[mt], sbase + SMEM_A_HI + off);
                ldmatrix_x4(al[mt], sbase + SMEM_A_LO + off);
            }
#pragma unroll
            for (int nt = 0; nt < 4; ++nt) {
                int row = kk + (lane & 15);
                uint32_t off = (uint32_t)(row * 128 + (wn0 + nt * 8) * 2);
                off ^= (uint32_t)(row & 7) << 4;
                ldmatrix_x2t(bh[nt], sbase + SMEM_B_HI + off);
                ldmatrix_x2t(bl[nt], sbase + SMEM_B_LO + off);
            }
#pragma unroll
            for (int mt = 0; mt < 2; ++mt)
#pragma unroll
                for (int nt = 0; nt < 4; ++nt) {
                    mma_bf16(d[mt][nt], ah[mt], bh[nt]);
                    mma_bf16(d[mt][nt], ah[mt], bl[nt]);
                    mma_bf16(d[mt][nt], al[mt], bh[nt]);
                }
        }
        __syncthreads();
    }

    // ---- epilogue: write fp32 Y1 ----
    const int group = lane >> 2, tig = lane & 3;
#pragma unroll
    for (int mt = 0; mt < 2; ++mt) {
#pragma unroll
        for (int nt = 0; nt < 4; ++nt) {
            int row = bm + wm0 + mt * 16 + group;
            int col = bn + wn0 + nt * 8 + tig * 2;
            float2 v01 = make_float2(d[mt][nt][0], d[mt][nt][1]);
            float2 v23 = make_float2(d[mt][nt][2], d[mt][nt][3]);
            *(float2*)&g_Y1[(size_t)row * DH + col] = v01;
            *(float2*)&g_Y1[(size_t)(row + 8) * DH + col] = v23;
        }
    }
}

// ---------------- prop1: P1[dst] += Y1[src] * (dinv[src]*dinv[dst]) --------
__global__ __launch_bounds__(256) void prop1_kernel(const int* __restrict__ src,
                                                    const int* __restrict__ dst) {
    int w = (blockIdx.x * blockDim.x + threadIdx.x) >> 5;
    int lane = threadIdx.x & 31;
    if (w >= NEDGES) return;
    int s = __ldg(&src[w]);
    int d = __ldg(&dst[w]);
    float nrm = g_dinv[s] * g_dinv[d];
    const float4* yrow = (const float4*)(g_Y1 + (size_t)s * DH);
    float* prow = g_P1 + (size_t)d * DH;
#pragma unroll
    for (int it = 0; it < 2; ++it) {
        int c = lane + it * 32;
        float4 v = __ldg(&yrow[c]);
        float* p = prow + (c << 2);
        asm volatile("red.global.add.v4.f32 [%0], {%1,%2,%3,%4};"
                     :: "l"(p), "f"(v.x * nrm), "f"(v.y * nrm),
                        "f"(v.z * nrm), "f"(v.w * nrm) : "memory");
    }
}

// ---------------- node fuse: h = relu(P1 + Y1*dinv^2 + b1); Y2 = h @ W2 ----
__global__ __launch_bounds__(256) void node2_kernel(const float* __restrict__ b1,
                                                    const float* __restrict__ W2) {
    int node = (blockIdx.x * blockDim.x + threadIdx.x) >> 5;
    int lane = threadIdx.x & 31;
    if (node >= NNODES) return;
    float di = g_dinv[node];
    float di2 = di * di;
    const float* prow = g_P1 + (size_t)node * DH;
    const float* yrow = g_Y1 + (size_t)node * DH;
    const float2* w2 = (const float2*)W2;
    float s0 = 0.f, s1 = 0.f;
#pragma unroll
    for (int j = 0; j < DH / 32; ++j) {
        int d = lane + j * 32;
        float h = prow[d] + yrow[d] * di2 + b1[d];
        h = fmaxf(h, 0.f);
        float2 w = __ldg(&w2[d]);
        s0 = fmaf(h, w.x, s0);
        s1 = fmaf(h, w.y, s1);
    }
#pragma unroll
    for (int off = 16; off > 0; off >>= 1) {
        s0 += __shfl_down_sync(0xffffffffu, s0, off);
        s1 += __shfl_down_sync(0xffffffffu, s1, off);
    }
    if (lane == 0) {
        g_Y2[node * 2 + 0] = s0;
        g_Y2[node * 2 + 1] = s1;
    }
}

// ---------------- prop2 ----------------------------------------------------
__global__ void prop2_kernel(const int* __restrict__ src, const int* __restrict__ dst) {
    int e = blockIdx.x * blockDim.x + threadIdx.x;
    if (e >= NEDGES) return;
    int s = src[e], d = dst[e];
    float nrm = g_dinv[s] * g_dinv[d];
    float2 y = ((const float2*)g_Y2)[s];
    float* p = g_eacc + (size_t)d * 2;
    asm volatile("red.global.add.v2.f32 [%0], {%1,%2};"
                 :: "l"(p), "f"(y.x * nrm), "f"(y.y * nrm) : "memory");
}

// ---------------- finalize emb ---------------------------------------------
__global__ void fin_kernel(const float* __restrict__ b2, float* __restrict__ out) {
    int i = blockIdx.x * blockDim.x + threadIdx.x;
    if (i >= NNODES) return;
    float di = g_dinv[i];
    float di2 = di * di;
    float2 y = ((const float2*)g_Y2)[i];
    float ex = g_eacc[2 * i + 0] + y.x * di2 + b2[0];
    float ey = g_eacc[2 * i + 1] + y.y * di2 + b2[1];
    g_ex[i] = ex;
    g_ey[i] = ey;
    out[2 * i + 0] = ex;
    out[2 * i + 1] = ey;
}

// ---------------- q: symmetric upper-triangular 64x64 tiles ----------------
__device__ __forceinline__ float qval(float dx, float dy) {
    float d2 = fmaf(dx, dx, dy * dy);
    float pw = __powf(d2, BETA);
    float q  = __fdividef(1.0f, fmaf(ALPHA, pw, 1.0f));
    return d2 > 0.0f ? q : 1.0f;
}

__global__ __launch_bounds__(256) void q_kernel(float* __restrict__ qout) {
    __shared__ float qs[64][65];
    int b = blockIdx.x;
    int r = (int)((257.0f - sqrtf(66049.0f - 8.0f * (float)b)) * 0.5f);
    while ((r + 1) * 128 - ((r + 1) * r) / 2 <= b) ++r;
    while (r * 128 - (r * (r - 1)) / 2 > b) --r;
    int S = r * 128 - (r * (r - 1)) / 2;
    int bi = r;
    int bj = r + (b - S);
    int ty = threadIdx.x >> 4, tx = threadIdx.x & 15;
    int r0 = ty * 4, c0 = tx * 4;
    bool diag = (bi == bj);

    float4 xj = *(const float4*)&g_ex[bj * 64 + c0];
    float4 yj = *(const float4*)&g_ey[bj * 64 + c0];
#pragma unroll
    for (int u = 0; u < 4; ++u) {
        float xi = g_ex[bi * 64 + r0 + u];
        float yi = g_ey[bi * 64 + r0 + u];
        float4 v;
        v.x = qval(xi - xj.x, yi - yj.x);
        v.y = qval(xi - xj.y, yi - yj.y);
        v.z = qval(xi - xj.z, yi - yj.z);
        v.w = qval(xi - xj.w, yi - yj.w);
        *(float4*)&qout[(size_t)(bi * 64 + r0 + u) * NNODES + bj * 64 + c0] = v;
        if (!diag) {
            qs[r0 + u][c0 + 0] = v.x;
            qs[r0 + u][c0 + 1] = v.y;
            qs[r0 + u][c0 + 2] = v.z;
            qs[r0 + u][c0 + 3] = v.w;
        }
    }
    if (!diag) {
        __syncthreads();
#pragma unroll
        for (int u = 0; u < 4; ++u) {
            float4 v;
            v.x = qs[c0 + 0][r0 + u];
            v.y = qs[c0 + 1][r0 + u];
            v.z = qs[c0 + 2][r0 + u];
            v.w = qs[c0 + 3][r0 + u];
            *(float4*)&qout[(size_t)(bj * 64 + r0 + u) * NNODES + bi * 64 + c0] = v;
        }
    }
}

// ---------------------------------------------------------------------------
extern "C" void kernel_launch(void* const* d_in, const int* in_sizes, int n_in,
                              void* d_out, int out_size) {
    const float* X  = (const float*)d_in[0];
    const int*   ei = (const int*)  d_in[1];
    const float* W1 = (const float*)d_in[2];
    const float* b1 = (const float*)d_in[3];
    const float* W2 = (const float*)d_in[4];
    const float* b2 = (const float*)d_in[5];
    float* out = (float*)d_out;
    (void)in_sizes; (void)n_in; (void)out_size;

    const int* src = ei;
    const int* dst = ei + NEDGES;

    zero_kernel<<<(NNODES * DH / 4 + 255) / 256, 256>>>();
    deg_kernel<<<NEDGES / 256, 256>>>(dst);
    dinv_kernel<<<NNODES / 256, 256>>>();
    gemm1_mma_kernel<<<dim3(DH / 64, NNODES / 128), 256, GEMM_SMEM>>>(X, W1);
    prop1_kernel<<<NEDGES * 32 / 256, 256>>>(src, dst);
    node2_kernel<<<NNODES * 32 / 256, 256>>>(b1, W2);
    prop2_kernel<<<NEDGES / 256, 256>>>(src, dst);
    fin_kernel<<<NNODES / 256, 256>>>(b2, out);
    q_kernel<<<128 * 129 / 2, 256>>>(out + NNODES * 2);
}